// round 16
// baseline (speedup 1.0000x reference)
#include <cuda_runtime.h>

static constexpr int D_CH  = 4096;   // channels
static constexpr int L_SEQ = 4096;   // sequence length
static constexpr int TPB   = 256;    // 8 warps; warp owns contiguous 512-elem segment
static constexpr int V4_PER_ROW = L_SEQ / 4;  // 1024 int4 per row
static constexpr int GRID  = 152 * 8;         // persistent: ~8 blocks per SM (152 SMs)

// pack low bytes of 4 int32 (each in [-128,127]) into one word: b0=a,b1=b,b2=c,b3=d
__device__ __forceinline__ int pack4(int a, int b, int c, int d) {
    const unsigned lo = __byte_perm((unsigned)a, (unsigned)b, 0x0040);
    const unsigned hi = __byte_perm((unsigned)c, (unsigned)d, 0x0040);
    return (int)__byte_perm(lo, hi, 0x5410);
}

__global__ void __launch_bounds__(TPB)
qconv_silu_kernel(const int4* __restrict__ x,      // int8 promoted to int32
                  const int4* __restrict__ w,      // [D,4] int32
                  const int*  __restrict__ bias,   // [D] int32
                  const float* __restrict__ p_sin,
                  const float* __restrict__ p_sw,
                  const float* __restrict__ p_sout,
                  const float* __restrict__ p_sb,
                  float4* __restrict__ out,        // float32 out
                  int n_rows)
{
    const int lane = threadIdx.x & 31;
    const int wp   = threadIdx.x >> 5;
    const int segb = 128 * wp;               // warp's first int4 within a row

    // Uniform scalars hoisted out of the row loop (loaded once per block)
    const float sxw     = __ldg(p_sin) * __ldg(p_sw);
    const float inv_out = 1.0f / __ldg(p_sout);
    const float sb      = __ldg(p_sb);
    const int   src     = (lane + 31) & 31;  // rotate-up: lane 0 <- lane 31

    // Persistent grid-stride over rows: kills wave-transition tails and lets
    // ptxas pipeline next-row loads under current-row compute/stores.
    for (int row = blockIdx.x; row < n_rows; row += GRID) {
        const int  d    = row & (D_CH - 1);
        const long rowb = (long)row * V4_PER_ROW;

        // Coalesced evict-first loads: 4 lines per LDG.128 (minimum wavefronts)
        int4 c[4];
#pragma unroll
        for (int k = 0; k < 4; ++k)
            c[k] = __ldcs(&x[rowb + segb + 32 * k + lane]);

        // Carry chunk preceding the warp segment (zeros at row start = causal
        // pad); only lane 31 (shuffle sender for lane 0) needs real data.
        int4 carry = make_int4(0, 0, 0, 0);
        if (lane == 31 && wp != 0)
            carry = __ldg(&x[rowb + segb - 1]);

        // Pack chunks and weights to bytes for dp4a
        int pk[4];
#pragma unroll
        for (int k = 0; k < 4; ++k)
            pk[k] = pack4(c[k].x, c[k].y, c[k].z, c[k].w);
        const int pc = pack4(carry.x, carry.y, carry.z, carry.w);

        const int4  wv4 = w[d];
        const int   wpk = pack4(wv4.x, wv4.y, wv4.z, wv4.w);  // b0=w0..b3=w3
        const float bf  = (float)bias[d] * sb;

#pragma unroll
        for (int k = 0; k < 4; ++k) {
            // previous packed chunk: lanes 1..31 <- neighbor's pk[k];
            // lane 0 <- lane31's pk[k-1] (carry for k==0)
            const int v  = (lane == 31) ? (k == 0 ? pc : pk[k - 1]) : pk[k];
            const int Pp = __shfl_sync(0xffffffffu, v, src);
            const int P  = pk[k];

            float4 o;
            float* op = (float*)&o;
#pragma unroll
            for (int j = 0; j < 4; ++j) {
                // window bytes (LSB..MSB) = x[l-3], x[l-2], x[l-1], x[l]
                const int win = (j == 3) ? P
                              : (int)__funnelshift_r((unsigned)Pp, (unsigned)P, 8 * (j + 1));
                // exact 4-tap cross-correlation in one dp4a (|acc| <= 65024)
                const int acc = __dp4a(win, wpk, 0);
                const float y = (float)acc * sxw + bf;
                // SiLU: y * sigmoid(y) via fast rcp; |y| <= ~7.8
                const float s = __fdividef(y, 1.0f + __expf(-y));
                // requant: half-even rounding matches jnp.round.
                // Lower clip provably never binds (silu >= -0.2785 -> r >= -5.6).
                const float r = rintf(s * inv_out);
                op[j] = fminf(r, 127.0f);
            }
            // streaming evict-first store
            __stcs(&out[rowb + segb + 32 * k + lane], o);
        }
    }
}

extern "C" void kernel_launch(void* const* d_in, const int* in_sizes, int n_in,
                              void* d_out, int out_size)
{
    const int4* x    = (const int4*)d_in[0];
    const int4* w    = (const int4*)d_in[1];
    const int*  bias = (const int*)d_in[2];
    const float* sin_ = (const float*)d_in[3];
    const float* sw_  = (const float*)d_in[4];
    const float* sout = (const float*)d_in[5];
    const float* sb_  = (const float*)d_in[6];

    const int rows = in_sizes[0] / L_SEQ;   // B*D = 8192
    qconv_silu_kernel<<<GRID, TPB>>>(x, w, bias, sin_, sw_, sout, sb_,
                                     (float4*)d_out, rows);
}

// round 17
// speedup vs baseline: 1.1001x; 1.1001x over previous
#include <cuda_runtime.h>

static constexpr int D_CH  = 4096;   // channels
static constexpr int L_SEQ = 4096;   // sequence length
static constexpr int TPB   = 256;    // 8 warps; warp owns contiguous 512-elem segment
static constexpr int V4_PER_ROW = L_SEQ / 4;  // 1024 int4 per row

// pack low bytes of 4 int32 (each in [-128,127]) into one word: b0=a,b1=b,b2=c,b3=d
__device__ __forceinline__ int pack4(int a, int b, int c, int d) {
    const unsigned lo = __byte_perm((unsigned)a, (unsigned)b, 0x0040);
    const unsigned hi = __byte_perm((unsigned)c, (unsigned)d, 0x0040);
    return (int)__byte_perm(lo, hi, 0x5410);
}

__global__ void __launch_bounds__(TPB)
qconv_silu_kernel(const int4* __restrict__ x,      // int8 promoted to int32
                  const int4* __restrict__ w,      // [D,4] int32
                  const int*  __restrict__ bias,   // [D] int32
                  const float* __restrict__ p_sin,
                  const float* __restrict__ p_sw,
                  const float* __restrict__ p_sout,
                  const float* __restrict__ p_sb,
                  float4* __restrict__ out)        // float32 out
{
    const int  row  = blockIdx.x;            // b*D + d
    const int  d    = row & (D_CH - 1);
    const int  lane = threadIdx.x & 31;
    const int  wp   = threadIdx.x >> 5;
    const long rowb = (long)row * V4_PER_ROW;
    const int  segb = 128 * wp;              // warp's first int4 within row

    // Coalesced evict-first loads: 4 lines per LDG.128 (minimum wavefronts)
    int4 c[4];
#pragma unroll
    for (int k = 0; k < 4; ++k)
        c[k] = __ldcs(&x[rowb + segb + 32 * k + lane]);

    // Carry chunk preceding the warp segment (zeros at row start = causal pad);
    // only lane 31 (shuffle sender for lane 0) needs real data.
    int4 carry = make_int4(0, 0, 0, 0);
    if (lane == 31 && wp != 0)
        carry = __ldg(&x[rowb + segb - 1]);

    // Pack chunks and weights to bytes for dp4a
    int pk[4];
#pragma unroll
    for (int k = 0; k < 4; ++k)
        pk[k] = pack4(c[k].x, c[k].y, c[k].z, c[k].w);
    const int pc = pack4(carry.x, carry.y, carry.z, carry.w);

    const int4  wv4 = w[d];
    const int   wpk = pack4(wv4.x, wv4.y, wv4.z, wv4.w);  // b0=w0..b3=w3
    const float sxw     = __ldg(p_sin) * __ldg(p_sw);
    const float bf      = (float)bias[d] * __ldg(p_sb);
    const float inv_out = 1.0f / __ldg(p_sout);

    const int src = (lane + 31) & 31;        // rotate-up: lane 0 receives from lane 31

#pragma unroll
    for (int k = 0; k < 4; ++k) {
        // previous packed chunk: lanes 1..31 <- neighbor's pk[k]; lane 0 <- lane31's pk[k-1]/carry
        const int v  = (lane == 31) ? (k == 0 ? pc : pk[k - 1]) : pk[k];
        const int Pp = __shfl_sync(0xffffffffu, v, src);
        const int P  = pk[k];

        float4 o;
        float* op = (float*)&o;
#pragma unroll
        for (int j = 0; j < 4; ++j) {
            // window bytes (LSB..MSB) = x[l-3], x[l-2], x[l-1], x[l]
            const int win = (j == 3) ? P
                          : (int)__funnelshift_r((unsigned)Pp, (unsigned)P, 8 * (j + 1));
            // exact 4-tap cross-correlation in one dp4a (|acc| <= 65024)
            const int acc = __dp4a(win, wpk, 0);
            const float y = (float)acc * sxw + bf;
            // SiLU: y * sigmoid(y) via fast rcp; |y| <= ~7.8
            const float s = __fdividef(y, 1.0f + __expf(-y));
            // requant: half-even rounding matches jnp.round.
            // Lower clip provably never binds (silu >= -0.2785 -> r >= -5.6).
            const float r = rintf(s * inv_out);
            op[j] = fminf(r, 127.0f);
        }
        // streaming evict-first store
        __stcs(&out[rowb + segb + 32 * k + lane], o);
    }
}

extern "C" void kernel_launch(void* const* d_in, const int* in_sizes, int n_in,
                              void* d_out, int out_size)
{
    const int4* x    = (const int4*)d_in[0];
    const int4* w    = (const int4*)d_in[1];
    const int*  bias = (const int*)d_in[2];
    const float* sin_ = (const float*)d_in[3];
    const float* sw_  = (const float*)d_in[4];
    const float* sout = (const float*)d_in[5];
    const float* sb_  = (const float*)d_in[6];

    const int rows = in_sizes[0] / L_SEQ;   // B*D = 8192
    qconv_silu_kernel<<<rows, TPB>>>(x, w, bias, sin_, sw_, sout, sb_,
                                     (float4*)d_out);
}